// round 2
// baseline (speedup 1.0000x reference)
#include <cuda_runtime.h>
#include <cstdint>

// ---------------- problem constants ----------------
#define BS   512
#define T_   100
#define ND   10
#define DS   6
#define HID  256
#define CAT  2816
#define H_SZ   (512*256)
#define Z_SZ   (512*2816)
#define DT_TOT (100*512*64)
#define WIH_SZ (1024*256)
#define W1H_SZ (2816*256)
#define WEFF_SZ (2816*64)
#define WC_SZ  (320*2816)

// ---------------- device scratch (allocation-free) ----------------
__device__ float g_h_pk[4*H_SZ];      // [parity][plane hi/lo]
__device__ float g_c[H_SZ];
__device__ float g_nxt_pk[2*H_SZ];    // [plane]
__device__ float g_z_pk[2*Z_SZ];
__device__ float g_dt_pk[2*DT_TOT];
__device__ float g_part[8*512*320];
__device__ float g_Wih_p[2*WIH_SZ];
__device__ float g_Whh_p[2*WIH_SZ];
__device__ float g_W1h_p[2*W1H_SZ];
__device__ float g_Weff_p[2*WEFF_SZ];
__device__ float g_Wc_p[2*WC_SZ];
__device__ float g_bg[1024];
__device__ float g_cb[2816];
__device__ float g_bc[320];

// ---------------- helpers ----------------
__device__ __forceinline__ float tf32r(float x) {
    uint32_t u; asm("cvt.rna.tf32.f32 %0, %1;" : "=r"(u) : "f"(x));
    return __uint_as_float(u);
}
__device__ __forceinline__ float sigm(float x) { return 1.f / (1.f + __expf(-x)); }

// A-operand fragment-packed address: (m,k) for m16n8k8 row-major A. K8 = K/8.
__device__ __forceinline__ size_t apk(int m, int k, int K8) {
    return ((size_t)(m >> 4) * K8 + (k >> 3)) * 128
         + ((((m & 7) << 2) | (k & 3)) << 2)
         + (((m >> 3) & 1) | (((k >> 2) & 1) << 1));
}
// B-operand fragment-packed address: (n,k), col-major B (k x n). K8 = K/8.
__device__ __forceinline__ size_t bpk(int n, int k, int K8) {
    return ((size_t)(n >> 3) * K8 + (k >> 3)) * 64
         + ((((n & 7) << 2) | (k & 3)) << 1)
         + ((k >> 2) & 1);
}

__device__ __forceinline__ void mma8(float (&d)[4], const float (&a)[4], const float (&b)[2]) {
    asm volatile(
        "mma.sync.aligned.m16n8k8.row.col.f32.tf32.tf32.f32 "
        "{%0,%1,%2,%3}, {%4,%5,%6,%7}, {%8,%9}, {%0,%1,%2,%3};\n"
        : "+f"(d[0]), "+f"(d[1]), "+f"(d[2]), "+f"(d[3])
        : "r"(__float_as_uint(a[0])), "r"(__float_as_uint(a[1])),
          "r"(__float_as_uint(a[2])), "r"(__float_as_uint(a[3])),
          "r"(__float_as_uint(b[0])), "r"(__float_as_uint(b[1])));
}

// ---------------- 3xTF32 packed GEMM segment ----------------
// Block: 128 threads = 4 warps in 2x2. BM=64. Warp tile 32 x (NT*8). BN = NT*16.
// Accumulates C[64 x BN] += A[m0:,:] * B(n0:,:)^T over k8 range.
template<int NT>
__device__ __forceinline__ void gemm_pk(
    const float* __restrict__ Ah, const float* __restrict__ Al,
    const float* __restrict__ Bh, const float* __restrict__ Bl,
    int K8A, int K8B, int k8beg, int k8cnt,
    int mt0, int nt0,
    float (&acc)[2][NT][4], float* sA, float* sB)
{
    const int tid  = threadIdx.x;
    const int lane = tid & 31;
    const int wm   = (tid >> 5) >> 1;
    const int wn   = (tid >> 5) & 1;
    const int BPL  = NT * 256;               // sB plane stride (floats)

    for (int kc = 0; kc < k8cnt; kc += 2) {
        __syncthreads();
        {   // stage A: 2 planes * 4 mtiles * 2 k8 * 128 = 2048 floats
            int f0 = tid << 4;
            int plane = f0 >> 10;
            int r = f0 & 1023;
            int mt = r >> 8, k8 = (r >> 7) & 1, off = r & 127;
            const float* src = (plane ? Al : Ah)
                + ((size_t)(mt0 + mt) * K8A + (k8beg + kc + k8)) * 128 + off;
            float* dst = sA + f0;
            #pragma unroll
            for (int i = 0; i < 4; i++)
                *(float4*)(dst + i*4) = *(const float4*)(src + i*4);
        }
        {   // stage B: 2 planes * 2NT ntiles * 2 k8 * 64 = 512*NT floats
            const int per = (512*NT) >> 7;   // 16 (NT=4) or 32 (NT=8)
            int f0 = tid * per;
            int plane = f0 / BPL;
            int r = f0 % BPL;
            int nt = r >> 7, k8 = (r >> 6) & 1, off = r & 63;
            const float* src = (plane ? Bl : Bh)
                + ((size_t)(nt0 + nt) * K8B + (k8beg + kc + k8)) * 64 + off;
            float* dst = sB + f0;
            #pragma unroll
            for (int i = 0; i < per/4; i++)
                *(float4*)(dst + i*4) = *(const float4*)(src + i*4);
        }
        __syncthreads();
        #pragma unroll
        for (int k8 = 0; k8 < 2; k8++) {
            float ah[2][4], al[2][4];
            #pragma unroll
            for (int mt = 0; mt < 2; mt++) {
                const float* pa = sA + ((wm*2 + mt)*2 + k8)*128 + lane*4;
                *(float4*)ah[mt] = *(const float4*)pa;
                *(float4*)al[mt] = *(const float4*)(pa + 1024);
            }
            float bh[NT][2], bl[NT][2];
            #pragma unroll
            for (int nt = 0; nt < NT; nt++) {
                const float* pb = sB + ((wn*NT + nt)*2 + k8)*64 + lane*2;
                bh[nt][0] = pb[0];     bh[nt][1] = pb[1];
                bl[nt][0] = pb[BPL];   bl[nt][1] = pb[BPL + 1];
            }
            #pragma unroll
            for (int mt = 0; mt < 2; mt++)
            #pragma unroll
            for (int nt = 0; nt < NT; nt++) {
                mma8(acc[mt][nt], ah[mt], bh[nt]);   // hi*hi
                mma8(acc[mt][nt], ah[mt], bl[nt]);   // hi*lo
                mma8(acc[mt][nt], al[mt], bh[nt]);   // lo*hi
            }
        }
    }
}

// ---------------- per-step kernels ----------------

// Fused gates GEMM + LSTM pointwise. Gate-interleaved columns p = j*4+g.
__global__ __launch_bounds__(128) void k_gates_lstm(int par)
{
    __shared__ float sm[4096];
    float acc[2][4][4] = {};
    const int m0 = blockIdx.x * 64, n0 = blockIdx.y * 64;
    gemm_pk<4>(g_nxt_pk, g_nxt_pk + H_SZ, g_Wih_p, g_Wih_p + WIH_SZ,
               32, 32, 0, 32, m0 >> 4, n0 >> 3, acc, sm, sm + 2048);
    const float* hp = g_h_pk + (size_t)par * 2 * H_SZ;
    gemm_pk<4>(hp, hp + H_SZ, g_Whh_p, g_Whh_p + WIH_SZ,
               32, 32, 0, 32, m0 >> 4, n0 >> 3, acc, sm, sm + 2048);
    __syncthreads();
    const int tid = threadIdx.x, lane = tid & 31;
    const int wm = (tid >> 5) >> 1, wn = (tid >> 5) & 1;
    #pragma unroll
    for (int mt = 0; mt < 2; mt++)
    #pragma unroll
    for (int nt = 0; nt < 4; nt++)
    #pragma unroll
    for (int r = 0; r < 4; r++) {
        int rl = wm*32 + mt*16 + (lane >> 2) + ((r >> 1) << 3);
        int cl = wn*32 + nt*8 + ((lane & 3) << 1) + (r & 1);
        sm[rl*64 + cl] = acc[mt][nt][r];
    }
    __syncthreads();
    float* hw = g_h_pk + (size_t)(par ^ 1) * 2 * H_SZ;
    #pragma unroll
    for (int i = 0; i < 8; i++) {
        int p = tid + (i << 7);               // 0..1023 -> 64 b x 16 j
        int bl = p >> 4, jl = p & 15;
        float4 g4 = *(float4*)&sm[bl*64 + (jl << 2)];
        float4 bb = *(const float4*)&g_bg[n0 + (jl << 2)];
        float ii = sigm(g4.x + bb.x);
        float ff = sigm(g4.y + bb.y);
        float gg = tanhf(g4.z + bb.z);
        float oo = sigm(g4.w + bb.w);
        int b = m0 + bl, j = (n0 >> 2) + jl;
        float c = ff * g_c[b*256 + j] + ii * gg;
        g_c[b*256 + j] = c;
        float h = oo * tanhf(c);
        float hi = tf32r(h);
        size_t a = apk(b, j, 32);
        hw[a] = hi;
        hw[H_SZ + a] = tf32r(h - hi);
    }
}

// z = relu(dt@Weff^T + h@W1h^T + cb); write hi/lo packed
__global__ __launch_bounds__(128) void k_z(int par, int t)
{
    __shared__ float sm[6144];
    float acc[2][8][4] = {};
    const int m0 = blockIdx.x * 64, n0 = blockIdx.y * 128;
    const float* dth = g_dt_pk + (size_t)t * (512*64);
    gemm_pk<8>(dth, dth + DT_TOT, g_Weff_p, g_Weff_p + WEFF_SZ,
               8, 8, 0, 8, m0 >> 4, n0 >> 3, acc, sm, sm + 2048);
    const float* hp = g_h_pk + (size_t)(par ^ 1) * 2 * H_SZ;
    gemm_pk<8>(hp, hp + H_SZ, g_W1h_p, g_W1h_p + W1H_SZ,
               32, 32, 0, 32, m0 >> 4, n0 >> 3, acc, sm, sm + 2048);
    const int tid = threadIdx.x, lane = tid & 31;
    const int wm = (tid >> 5) >> 1, wn = (tid >> 5) & 1;
    #pragma unroll
    for (int mt = 0; mt < 2; mt++)
    #pragma unroll
    for (int nt = 0; nt < 8; nt++) {
        int nb = n0 + wn*64 + nt*8 + ((lane & 3) << 1);
        float2 c2 = *(const float2*)&g_cb[nb];
        #pragma unroll
        for (int r = 0; r < 4; r++) {
            int row = m0 + wm*32 + mt*16 + (lane >> 2) + ((r >> 1) << 3);
            int col = nb + (r & 1);
            float v = acc[mt][nt][r] + ((r & 1) ? c2.y : c2.x);
            v = fmaxf(v, 0.f);
            float hi = tf32r(v);
            size_t a = apk(row, col, 352);
            g_z_pk[a] = hi;
            g_z_pk[Z_SZ + a] = tf32r(v - hi);
        }
    }
}

// split-K partials of [W2;Wv] GEMM
__global__ __launch_bounds__(128) void k_nxt()
{
    __shared__ float sm[4096];
    float acc[2][4][4] = {};
    const int m0 = blockIdx.x * 64, n0 = blockIdx.y * 64, s = blockIdx.z;
    gemm_pk<4>(g_z_pk, g_z_pk + Z_SZ, g_Wc_p, g_Wc_p + WC_SZ,
               352, 352, s * 44, 44, m0 >> 4, n0 >> 3, acc, sm, sm + 2048);
    const int tid = threadIdx.x, lane = tid & 31;
    const int wm = (tid >> 5) >> 1, wn = (tid >> 5) & 1;
    float* pp = g_part + (size_t)s * 512 * 320;
    #pragma unroll
    for (int mt = 0; mt < 2; mt++)
    #pragma unroll
    for (int nt = 0; nt < 4; nt++)
    #pragma unroll
    for (int r = 0; r < 4; r++) {
        int row = m0 + wm*32 + mt*16 + (lane >> 2) + ((r >> 1) << 3);
        int col = n0 + wn*32 + nt*8 + ((lane & 3) << 1) + (r & 1);
        pp[(size_t)row * 320 + col] = acc[mt][nt][r];
    }
}

// deterministic reduce + activations
__global__ void k_reduce(float* __restrict__ out, int t)
{
    int gt = blockIdx.x * blockDim.x + threadIdx.x;
    if (gt >= 512 * 266) return;
    int b = gt / 266, n = gt % 266;
    float v = g_bc[n];
    #pragma unroll
    for (int s = 0; s < 8; s++)
        v += g_part[((size_t)s * 512 + b) * 320 + n];
    if (n < 256) {
        float r = fmaxf(v, 0.f);
        float hi = tf32r(r);
        size_t a = apk(b, n, 32);
        g_nxt_pk[a] = hi;
        g_nxt_pk[H_SZ + a] = tf32r(r - hi);
    } else {
        out[(size_t)b * (T_*ND) + t*ND + (n - 256)] = 1.f / (1.f + __expf(-v));
    }
}

// ---------------- one-time precompute ----------------
__global__ void k_pack_rnn(const float* __restrict__ Wih, const float* __restrict__ Whh,
                           const float* __restrict__ bih, const float* __restrict__ bhh)
{
    int idx = blockIdx.x * 256 + threadIdx.x;
    if (idx >= 1024*256) return;
    int p = idx >> 8, k = idx & 255;
    int j = p >> 2, g = p & 3;
    size_t a = bpk(p, k, 32);
    float w = Wih[(size_t)(g*256 + j) * 256 + k];
    float hi = tf32r(w);
    g_Wih_p[a] = hi; g_Wih_p[WIH_SZ + a] = tf32r(w - hi);
    w = Whh[(size_t)(g*256 + j) * 256 + k];
    hi = tf32r(w);
    g_Whh_p[a] = hi; g_Whh_p[WIH_SZ + a] = tf32r(w - hi);
    if (k == 0) g_bg[p] = bih[g*256 + j] + bhh[g*256 + j];
}

__global__ void k_pack_w1h(const float* __restrict__ W1)
{
    int idx = blockIdx.x * 256 + threadIdx.x;
    if (idx >= 2816*256) return;
    int n = idx >> 8, k = idx & 255;
    float w = W1[(size_t)n * 2816 + 2560 + k];
    float hi = tf32r(w);
    size_t a = bpk(n, k, 32);
    g_W1h_p[a] = hi; g_W1h_p[W1H_SZ + a] = tf32r(w - hi);
}

__global__ void k_cb(const float* __restrict__ W1, const float* __restrict__ b1,
                     const float* __restrict__ bd)
{
    int n = blockIdx.x * 256 + threadIdx.x;
    if (n >= 2816) return;
    float v = b1[n];
    const float* w = W1 + (size_t)n * 2816;
    for (int i = 0; i < 2560; i++) v += w[i] * bd[i & 255];
    g_cb[n] = v;
}

__global__ void k_weff(const float* __restrict__ W1, const float* __restrict__ Wd)
{
    int idx = blockIdx.x * 256 + threadIdx.x;
    if (idx >= 2816*64) return;
    int n = idx >> 6, kk = idx & 63;
    float v = 0.f;
    if (kk < 60) {
        int nd = kk / 6, d = kk - nd*6;
        const float* w = W1 + (size_t)n * 2816 + nd * 256;
        for (int i = 0; i < 256; i++) v += w[i] * Wd[i*6 + d];
    }
    float hi = tf32r(v);
    size_t a = bpk(n, kk, 8);
    g_Weff_p[a] = hi; g_Weff_p[WEFF_SZ + a] = tf32r(v - hi);
}

__global__ void k_pack_wc(const float* __restrict__ W2, const float* __restrict__ Wv,
                          const float* __restrict__ b2, const float* __restrict__ bv)
{
    int idx = blockIdx.x * 256 + threadIdx.x;
    if (idx >= 320*2816) return;
    int n = idx / 2816, k = idx - n*2816;
    float v = 0.f;
    if (n < 256)      v = W2[(size_t)n * 2816 + k];
    else if (n < 266) v = Wv[(size_t)(n - 256) * 2816 + k];
    float hi = tf32r(v);
    size_t a = bpk(n, k, 352);
    g_Wc_p[a] = hi; g_Wc_p[WC_SZ + a] = tf32r(v - hi);
    if (k == 0) g_bc[n] = (n < 256) ? b2[n] : ((n < 266) ? bv[n - 256] : 0.f);
}

__global__ void k_pack_dt(const float* __restrict__ desc)
{
    int idx = blockIdx.x * 256 + threadIdx.x;
    if (idx >= 100*512*64) return;
    int t = idx >> 15, b = (idx >> 6) & 511, kk = idx & 63;
    float v = (kk < 60) ? desc[((size_t)b * 100 + t) * 60 + kk] : 0.f;
    float hi = tf32r(v);
    size_t a = (size_t)t * 32768 + apk(b, kk, 8);
    g_dt_pk[a] = hi; g_dt_pk[DT_TOT + a] = tf32r(v - hi);
}

__global__ void k_init()
{
    int i = blockIdx.x * 256 + threadIdx.x;
    if (i < 2*H_SZ)            g_h_pk[i] = 0.f;            // parity 0, both planes
    else if (i < 3*H_SZ)       g_c[i - 2*H_SZ] = 0.f;
    else if (i < 5*H_SZ)       g_nxt_pk[i - 3*H_SZ] = 0.f;
}

// ---------------- launch ----------------
extern "C" void kernel_launch(void* const* d_in, const int* in_sizes, int n_in,
                              void* d_out, int out_size)
{
    const float* desc = (const float*)d_in[0];
    const float* Wd   = (const float*)d_in[1];
    const float* bd   = (const float*)d_in[2];
    const float* W1   = (const float*)d_in[3];
    const float* b1   = (const float*)d_in[4];
    const float* W2   = (const float*)d_in[5];
    const float* b2   = (const float*)d_in[6];
    const float* Wv   = (const float*)d_in[7];
    const float* bv   = (const float*)d_in[8];
    const float* Wih  = (const float*)d_in[9];
    const float* Whh  = (const float*)d_in[10];
    const float* bih  = (const float*)d_in[11];
    const float* bhh  = (const float*)d_in[12];
    float* out = (float*)d_out;

    k_pack_rnn<<<1024, 256>>>(Wih, Whh, bih, bhh);
    k_pack_w1h<<<2816, 256>>>(W1);
    k_cb      <<<11,   256>>>(W1, b1, bd);
    k_weff    <<<704,  256>>>(W1, Wd);
    k_pack_wc <<<3520, 256>>>(W2, Wv, b2, bv);
    k_pack_dt <<<12800,256>>>(desc);
    k_init    <<<2560, 256>>>();

    for (int t = 0; t < T_; t++) {
        int par = t & 1;
        k_gates_lstm<<<dim3(8, 16),    128>>>(par);
        k_z         <<<dim3(8, 22),    128>>>(par, t);
        k_nxt       <<<dim3(8, 5, 8),  128>>>();
        k_reduce    <<<532, 256>>>(out, t);
    }
}

// round 3
// speedup vs baseline: 3.1984x; 3.1984x over previous
#include <cuda_runtime.h>
#include <cuda_bf16.h>
#include <cstdint>

#define T_ 100
// plane sizes in 32-bit words (each word = bf16x2, k-even in low half)
#define H_PL    65536      // 512x256: (512/16)*16*128
#define Z_PL    720896     // 512x2816: 32*176*128
#define DT_T    16384      // per-t dt words: 32*4*128
#define DT_PL   1638400    // 100*DT_T
#define WIH_PL  131072     // 1024x256 B-layout: 128*16*64
#define W1H_PL  360448     // 2816x256: 352*16*64
#define WEFF_PL 90112      // 2816x64: 352*4*64
#define WC_PL   450560     // 320x2816: 40*176*64

__device__ __align__(16) uint32_t g_h_pk[4*H_PL];     // [parity][plane hi/lo]
__device__ __align__(16) uint32_t g_nxt_pk[2*H_PL];   // [plane]
__device__ __align__(16) uint32_t g_z_pk[2*Z_PL];
__device__ __align__(16) uint32_t g_dt_pk[2*DT_PL];
__device__ __align__(16) uint32_t g_Wih_p[2*WIH_PL];
__device__ __align__(16) uint32_t g_Whh_p[2*WIH_PL];
__device__ __align__(16) uint32_t g_W1h_p[2*W1H_PL];
__device__ __align__(16) uint32_t g_Weff_p[2*WEFF_PL];
__device__ __align__(16) uint32_t g_Wc_p[2*WC_PL];
__device__ __align__(16) float g_c[512*256];
__device__ __align__(16) float g_part[4*512*320];
__device__ __align__(16) float g_bg[1024];
__device__ __align__(16) float g_cb[2816];
__device__ __align__(16) float g_bc[320];

// ---------------- helpers ----------------
__device__ __forceinline__ float sigm(float x) { return 1.f / (1.f + __expf(-x)); }
__device__ __forceinline__ uint16_t b16c(float x){ __nv_bfloat16 b = __float2bfloat16(x); return *(uint16_t*)&b; }
__device__ __forceinline__ float b16f(uint16_t u){ __nv_bfloat16 b = *(__nv_bfloat16*)&u; return __bfloat162float(b); }
__device__ __forceinline__ void bsplit(float x, uint16_t& h, uint16_t& l){
    h = b16c(x); l = b16c(x - b16f(h));
}
__device__ __forceinline__ uint32_t pk2(uint16_t e0, uint16_t e1){ return (uint32_t)e0 | ((uint32_t)e1 << 16); }

// A-operand word index for m16n8k16 row-major A. k2 = k/2 (word idx), K16 = K/16.
__device__ __forceinline__ size_t awrd(int m, int k2, int K16){
    return ((size_t)((m >> 4) * K16 + (k2 >> 3))) * 128
         + ((((m & 7) << 2) | (k2 & 3)) << 2)
         + (((m >> 3) & 1) | (((k2 >> 2) & 1) << 1));
}
// B-operand word index (N x K), col fragment.
__device__ __forceinline__ size_t bwrd(int n, int k2, int K16){
    return ((size_t)((n >> 3) * K16 + (k2 >> 3))) * 64
         + ((((n & 7) << 2) | (k2 & 3)) << 1)
         + ((k2 >> 2) & 1);
}

__device__ __forceinline__ void mma16(float (&d)[4], const uint32_t (&a)[4], const uint32_t (&b)[2]){
    asm volatile(
        "mma.sync.aligned.m16n8k16.row.col.f32.bf16.bf16.f32 "
        "{%0,%1,%2,%3}, {%4,%5,%6,%7}, {%8,%9}, {%0,%1,%2,%3};\n"
        : "+f"(d[0]), "+f"(d[1]), "+f"(d[2]), "+f"(d[3])
        : "r"(a[0]), "r"(a[1]), "r"(a[2]), "r"(a[3]), "r"(b[0]), "r"(b[1]));
}

// ---------------- pipelined bf16x3 GEMM segment ----------------
// 256 thr = 8 warps (wm 0..1, wn 0..3). BM=64 (4 A-tiles). BN = 32*NT (4*NT B-tiles).
template<int NT>
__device__ __forceinline__ void gemm_bf16(
    const uint32_t* __restrict__ Ah, const uint32_t* __restrict__ Al,
    const uint32_t* __restrict__ Bh, const uint32_t* __restrict__ Bl,
    int K16A, int K16B, int ktbeg, int ktcnt,
    int mt0, int nt0, float (&acc)[2][NT][4], uint32_t* smem)
{
    const int tid = threadIdx.x, lane = tid & 31;
    const int wm = (tid >> 5) >> 2, wn = (tid >> 5) & 3;
    const int BW  = 256 * NT;        // B words per plane per stage
    const int STG = 1024 + 2 * BW;   // words per stage
    const int NCH = STG >> 2;        // 16B chunks per stage
    uint32_t sb = (uint32_t)__cvta_generic_to_shared(smem);

    auto issue = [&](int kt, int s){
        #pragma unroll
        for (int i = 0; i < NCH / 256; i++){
            int c = tid + i * 256;
            const uint32_t* src; uint32_t dst;
            if (c < 256){
                int pl = c >> 7, r = c & 127, mt = r >> 5, off = (r & 31) << 2;
                src = (pl ? Al : Ah) + ((size_t)(mt0 + mt) * K16A + kt) * 128 + off;
                dst = sb + (uint32_t)((s * STG + pl * 512 + mt * 128 + off) << 2);
            } else {
                int cb = c - 256;
                int pl = cb >= 64 * NT;
                int r  = pl ? cb - 64 * NT : cb;
                int nt = r >> 4, off = (r & 15) << 2;
                src = (pl ? Bl : Bh) + ((size_t)(nt0 + nt) * K16B + kt) * 64 + off;
                dst = sb + (uint32_t)((s * STG + 1024 + pl * BW + nt * 64 + off) << 2);
            }
            asm volatile("cp.async.cg.shared.global [%0], [%1], 16;\n" :: "r"(dst), "l"(src));
        }
        asm volatile("cp.async.commit_group;\n");
    };

    issue(ktbeg, 0);
    for (int i = 0; i < ktcnt; i++){
        if (i + 1 < ktcnt){ issue(ktbeg + i + 1, (i + 1) & 1); asm volatile("cp.async.wait_group 1;\n"); }
        else              { asm volatile("cp.async.wait_group 0;\n"); }
        __syncthreads();
        const uint32_t* sA = smem + (i & 1) * STG;
        const uint32_t* sB = sA + 1024;
        uint32_t ah[2][4], al[2][4];
        #pragma unroll
        for (int mt = 0; mt < 2; mt++){
            const uint32_t* p = sA + (wm * 2 + mt) * 128 + lane * 4;
            *(uint4*)ah[mt] = *(const uint4*)p;
            *(uint4*)al[mt] = *(const uint4*)(p + 512);
        }
        uint32_t bh[NT][2], bl[NT][2];
        #pragma unroll
        for (int nt = 0; nt < NT; nt++){
            const uint32_t* q = sB + (wn * NT + nt) * 64 + lane * 2;
            bh[nt][0] = q[0];    bh[nt][1] = q[1];
            bl[nt][0] = q[BW];   bl[nt][1] = q[BW + 1];
        }
        #pragma unroll
        for (int mt = 0; mt < 2; mt++)
        #pragma unroll
        for (int nt = 0; nt < NT; nt++){
            mma16(acc[mt][nt], ah[mt], bh[nt]);   // hi*hi
            mma16(acc[mt][nt], ah[mt], bl[nt]);   // hi*lo
            mma16(acc[mt][nt], al[mt], bh[nt]);   // lo*hi
        }
        __syncthreads();
    }
}

// ---------------- per-step kernels ----------------

// gates = nxt@Wih^T + h@Whh^T (+bias), fused LSTM pointwise, writes h (bf16 hi/lo packed)
__global__ __launch_bounds__(256) void k_gates_lstm(int par)
{
    __shared__ __align__(16) uint32_t sm[4096];
    float acc[2][2][4] = {};
    const int mt0 = blockIdx.x * 4, nt0 = blockIdx.y * 8;
    gemm_bf16<2>(g_nxt_pk, g_nxt_pk + H_PL, g_Wih_p, g_Wih_p + WIH_PL, 16, 16, 0, 16, mt0, nt0, acc, sm);
    const uint32_t* hp = g_h_pk + (size_t)par * 2 * H_PL;
    gemm_bf16<2>(hp, hp + H_PL, g_Whh_p, g_Whh_p + WIH_PL, 16, 16, 0, 16, mt0, nt0, acc, sm);
    float* smf = (float*)sm;
    const int tid = threadIdx.x, lane = tid & 31;
    const int wm = (tid >> 5) >> 2, wn = (tid >> 5) & 3;
    #pragma unroll
    for (int mt = 0; mt < 2; mt++)
    #pragma unroll
    for (int nt = 0; nt < 2; nt++)
    #pragma unroll
    for (int r = 0; r < 4; r++){
        int rl = wm * 32 + mt * 16 + (lane >> 2) + ((r >> 1) << 3);
        int cl = wn * 16 + nt * 8 + ((lane & 3) << 1) + (r & 1);
        smf[rl * 64 + cl] = acc[mt][nt][r];
    }
    __syncthreads();
    const int m0 = blockIdx.x * 64, n0 = blockIdx.y * 64;
    uint32_t* hw = g_h_pk + (size_t)(par ^ 1) * 2 * H_PL;
    #pragma unroll
    for (int it = 0; it < 2; it++){
        int p = tid + it * 256;           // [0,512): 64 rows x 8 j-pairs
        int bl = p >> 3, jp = p & 7;
        float* gp = smf + bl * 64 + jp * 8;
        float4 ga = *(float4*)gp;
        float4 gb = *(float4*)(gp + 4);
        float4 ba = *(const float4*)&g_bg[n0 + jp * 8];
        float4 bb = *(const float4*)&g_bg[n0 + jp * 8 + 4];
        int b = m0 + bl;
        int j0 = (n0 >> 2) + jp * 2;
        float2 cc = *(float2*)&g_c[b * 256 + j0];
        float i0 = sigm(ga.x + ba.x), f0 = sigm(ga.y + ba.y);
        float g0 = tanhf(ga.z + ba.z), o0 = sigm(ga.w + ba.w);
        float i1 = sigm(gb.x + bb.x), f1 = sigm(gb.y + bb.y);
        float g1 = tanhf(gb.z + bb.z), o1 = sigm(gb.w + bb.w);
        float c0 = f0 * cc.x + i0 * g0, c1 = f1 * cc.y + i1 * g1;
        *(float2*)&g_c[b * 256 + j0] = make_float2(c0, c1);
        float h0 = o0 * tanhf(c0), h1 = o1 * tanhf(c1);
        uint16_t h0h, h0l, h1h, h1l;
        bsplit(h0, h0h, h0l); bsplit(h1, h1h, h1l);
        size_t w = awrd(b, j0 >> 1, 16);
        hw[w]        = pk2(h0h, h1h);
        hw[H_PL + w] = pk2(h0l, h1l);
    }
}

// z = relu(dt@Weff^T + h@W1h^T + cb), writes bf16 hi/lo packed
__global__ __launch_bounds__(256) void k_z(int par, int t)
{
    __shared__ __align__(16) uint32_t sm[6144];
    float acc[2][4][4] = {};
    const int mt0 = blockIdx.x * 4, nt0 = blockIdx.y * 16;
    const uint32_t* dt = g_dt_pk + (size_t)t * DT_T;
    gemm_bf16<4>(dt, dt + DT_PL, g_Weff_p, g_Weff_p + WEFF_PL, 4, 4, 0, 4, mt0, nt0, acc, sm);
    const uint32_t* hp = g_h_pk + (size_t)(par ^ 1) * 2 * H_PL;
    gemm_bf16<4>(hp, hp + H_PL, g_W1h_p, g_W1h_p + W1H_PL, 16, 16, 0, 16, mt0, nt0, acc, sm);
    const int tid = threadIdx.x, lane = tid & 31;
    const int wm = (tid >> 5) >> 2, wn = (tid >> 5) & 3;
    const int m0 = blockIdx.x * 64, n0 = blockIdx.y * 128;
    #pragma unroll
    for (int mt = 0; mt < 2; mt++){
        int r0 = m0 + wm * 32 + mt * 16 + (lane >> 2);
        #pragma unroll
        for (int nt = 0; nt < 4; nt++){
            int col = n0 + wn * 32 + nt * 8 + ((lane & 3) << 1);
            float2 cb2 = *(const float2*)&g_cb[col];
            int k2 = col >> 1;
            float v0 = fmaxf(acc[mt][nt][0] + cb2.x, 0.f);
            float v1 = fmaxf(acc[mt][nt][1] + cb2.y, 0.f);
            float v2 = fmaxf(acc[mt][nt][2] + cb2.x, 0.f);
            float v3 = fmaxf(acc[mt][nt][3] + cb2.y, 0.f);
            uint16_t h0, l0, h1, l1;
            bsplit(v0, h0, l0); bsplit(v1, h1, l1);
            size_t w = awrd(r0, k2, 176);
            g_z_pk[w] = pk2(h0, h1); g_z_pk[Z_PL + w] = pk2(l0, l1);
            bsplit(v2, h0, l0); bsplit(v3, h1, l1);
            w = awrd(r0 + 8, k2, 176);
            g_z_pk[w] = pk2(h0, h1); g_z_pk[Z_PL + w] = pk2(l0, l1);
        }
    }
}

// split-K(4) partials of z @ [W2;Wv]^T
__global__ __launch_bounds__(256) void k_nxt()
{
    __shared__ __align__(16) uint32_t sm[4096];
    float acc[2][2][4] = {};
    const int mt0 = blockIdx.x * 4, nt0 = blockIdx.y * 8, s = blockIdx.z;
    gemm_bf16<2>(g_z_pk, g_z_pk + Z_PL, g_Wc_p, g_Wc_p + WC_PL, 176, 176, s * 44, 44, mt0, nt0, acc, sm);
    const int tid = threadIdx.x, lane = tid & 31;
    const int wm = (tid >> 5) >> 2, wn = (tid >> 5) & 3;
    const int m0 = blockIdx.x * 64, n0 = blockIdx.y * 64;
    float* pp = g_part + (size_t)s * 512 * 320;
    #pragma unroll
    for (int mt = 0; mt < 2; mt++)
    #pragma unroll
    for (int nt = 0; nt < 2; nt++){
        int row = m0 + wm * 32 + mt * 16 + (lane >> 2);
        int col = n0 + wn * 16 + nt * 8 + ((lane & 3) << 1);
        *(float2*)&pp[(size_t)row * 320 + col]       = make_float2(acc[mt][nt][0], acc[mt][nt][1]);
        *(float2*)&pp[(size_t)(row + 8) * 320 + col] = make_float2(acc[mt][nt][2], acc[mt][nt][3]);
    }
}

// deterministic reduce + activations; writes packed nxt and output attention
__global__ void k_reduce(float* __restrict__ out, int t)
{
    int i = blockIdx.x * 256 + threadIdx.x;
    if (i >= 512 * 133) return;
    int b = i / 133, q = i - b * 133;
    if (q < 128){
        int n = q * 2;
        float v0 = g_bc[n], v1 = g_bc[n + 1];
        #pragma unroll
        for (int s = 0; s < 4; s++){
            float2 p = *(const float2*)&g_part[((size_t)s * 512 + b) * 320 + n];
            v0 += p.x; v1 += p.y;
        }
        v0 = fmaxf(v0, 0.f); v1 = fmaxf(v1, 0.f);
        uint16_t h0, l0, h1, l1;
        bsplit(v0, h0, l0); bsplit(v1, h1, l1);
        size_t w = awrd(b, q, 16);
        g_nxt_pk[w]        = pk2(h0, h1);
        g_nxt_pk[H_PL + w] = pk2(l0, l1);
    } else {
        int p = q - 128;
        int n = 256 + p * 2;
        float v0 = g_bc[n], v1 = g_bc[n + 1];
        #pragma unroll
        for (int s = 0; s < 4; s++){
            v0 += g_part[((size_t)s * 512 + b) * 320 + n];
            v1 += g_part[((size_t)s * 512 + b) * 320 + n + 1];
        }
        out[(size_t)b * 1000 + t * 10 + p * 2]     = 1.f / (1.f + __expf(-v0));
        out[(size_t)b * 1000 + t * 10 + p * 2 + 1] = 1.f / (1.f + __expf(-v1));
    }
}

// ---------------- one-time precompute ----------------
__global__ void k_pack_rnn(const float* __restrict__ Wih, const float* __restrict__ Whh,
                           const float* __restrict__ bih, const float* __restrict__ bhh)
{
    int idx = blockIdx.x * 256 + threadIdx.x;
    if (idx >= 1024 * 128) return;
    int p = idx >> 7, k2 = idx & 127;
    int j = p >> 2, g = p & 3;
    int row = g * 256 + j;
    size_t w = bwrd(p, k2, 16);
    uint16_t h0, l0, h1, l1;
    float a0 = Wih[(size_t)row * 256 + 2 * k2], a1 = Wih[(size_t)row * 256 + 2 * k2 + 1];
    bsplit(a0, h0, l0); bsplit(a1, h1, l1);
    g_Wih_p[w] = pk2(h0, h1); g_Wih_p[WIH_PL + w] = pk2(l0, l1);
    a0 = Whh[(size_t)row * 256 + 2 * k2]; a1 = Whh[(size_t)row * 256 + 2 * k2 + 1];
    bsplit(a0, h0, l0); bsplit(a1, h1, l1);
    g_Whh_p[w] = pk2(h0, h1); g_Whh_p[WIH_PL + w] = pk2(l0, l1);
    if (k2 == 0) g_bg[p] = bih[row] + bhh[row];
}

__global__ void k_pack_w1h(const float* __restrict__ W1)
{
    int idx = blockIdx.x * 256 + threadIdx.x;
    if (idx >= 2816 * 128) return;
    int n = idx >> 7, k2 = idx & 127;
    float a0 = W1[(size_t)n * 2816 + 2560 + 2 * k2];
    float a1 = W1[(size_t)n * 2816 + 2560 + 2 * k2 + 1];
    uint16_t h0, l0, h1, l1;
    bsplit(a0, h0, l0); bsplit(a1, h1, l1);
    size_t w = bwrd(n, k2, 16);
    g_W1h_p[w] = pk2(h0, h1); g_W1h_p[W1H_PL + w] = pk2(l0, l1);
}

__global__ void k_cb(const float* __restrict__ W1, const float* __restrict__ b1,
                     const float* __restrict__ bd)
{
    int n = blockIdx.x * 256 + threadIdx.x;
    if (n >= 2816) return;
    float v = b1[n];
    const float* w = W1 + (size_t)n * 2816;
    for (int i = 0; i < 2560; i++) v += w[i] * bd[i & 255];
    g_cb[n] = v;
}

__global__ void k_weff(const float* __restrict__ W1, const float* __restrict__ Wd)
{
    int idx = blockIdx.x * 256 + threadIdx.x;
    if (idx >= 2816 * 32) return;
    int n = idx >> 5, k2 = idx & 31;
    float v[2] = {0.f, 0.f};
    #pragma unroll
    for (int e = 0; e < 2; e++){
        int kk = 2 * k2 + e;
        if (kk < 60){
            int nd = kk / 6, d = kk - nd * 6;
            const float* w = W1 + (size_t)n * 2816 + nd * 256;
            float s = 0.f;
            for (int i = 0; i < 256; i++) s += w[i] * Wd[i * 6 + d];
            v[e] = s;
        }
    }
    uint16_t h0, l0, h1, l1;
    bsplit(v[0], h0, l0); bsplit(v[1], h1, l1);
    size_t w = bwrd(n, k2, 4);
    g_Weff_p[w] = pk2(h0, h1); g_Weff_p[WEFF_PL + w] = pk2(l0, l1);
}

__global__ void k_pack_wc(const float* __restrict__ W2, const float* __restrict__ Wv,
                          const float* __restrict__ b2, const float* __restrict__ bv)
{
    int idx = blockIdx.x * 256 + threadIdx.x;
    if (idx >= 320 * 1408) return;
    int n = idx / 1408, k2 = idx - n * 1408;
    int k = 2 * k2;
    float a0 = 0.f, a1 = 0.f;
    if (n < 256){ a0 = W2[(size_t)n * 2816 + k]; a1 = W2[(size_t)n * 2816 + k + 1]; }
    else if (n < 266){ a0 = Wv[(size_t)(n - 256) * 2816 + k]; a1 = Wv[(size_t)(n - 256) * 2816 + k + 1]; }
    uint16_t h0, l0, h1, l1;
    bsplit(a0, h0, l0); bsplit(a1, h1, l1);
    size_t w = bwrd(n, k2, 176);
    g_Wc_p[w] = pk2(h0, h1); g_Wc_p[WC_PL + w] = pk2(l0, l1);
    if (k2 == 0) g_bc[n] = (n < 256) ? b2[n] : ((n < 266) ? bv[n - 256] : 0.f);
}

__global__ void k_pack_dt(const float* __restrict__ desc)
{
    int idx = blockIdx.x * 256 + threadIdx.x;
    if (idx >= 100 * 512 * 32) return;
    int t = idx / 16384, r = idx - t * 16384;
    int b = r >> 5, k2 = r & 31;
    int kk = 2 * k2;
    float a0 = (kk < 60)     ? desc[((size_t)b * 100 + t) * 60 + kk]     : 0.f;
    float a1 = (kk + 1 < 60) ? desc[((size_t)b * 100 + t) * 60 + kk + 1] : 0.f;
    uint16_t h0, l0, h1, l1;
    bsplit(a0, h0, l0); bsplit(a1, h1, l1);
    size_t w = (size_t)t * DT_T + awrd(b, k2, 4);
    g_dt_pk[w] = pk2(h0, h1); g_dt_pk[DT_PL + w] = pk2(l0, l1);
}

__global__ void k_init()
{
    int i = blockIdx.x * 256 + threadIdx.x;
    if (i < 2 * H_PL)            g_h_pk[i] = 0u;               // parity 0, both planes
    else if (i < 4 * H_PL)       g_nxt_pk[i - 2 * H_PL] = 0u;
    else if (i < 4 * H_PL + 512 * 256) g_c[i - 4 * H_PL] = 0.f;
}

// ---------------- launch ----------------
extern "C" void kernel_launch(void* const* d_in, const int* in_sizes, int n_in,
                              void* d_out, int out_size)
{
    const float* desc = (const float*)d_in[0];
    const float* Wd   = (const float*)d_in[1];
    const float* bd   = (const float*)d_in[2];
    const float* W1   = (const float*)d_in[3];
    const float* b1   = (const float*)d_in[4];
    const float* W2   = (const float*)d_in[5];
    const float* b2   = (const float*)d_in[6];
    const float* Wv   = (const float*)d_in[7];
    const float* bv   = (const float*)d_in[8];
    const float* Wih  = (const float*)d_in[9];
    const float* Whh  = (const float*)d_in[10];
    const float* bih  = (const float*)d_in[11];
    const float* bhh  = (const float*)d_in[12];
    float* out = (float*)d_out;

    k_pack_rnn<<<512,  256>>>(Wih, Whh, bih, bhh);
    k_pack_w1h<<<1408, 256>>>(W1);
    k_cb      <<<11,   256>>>(W1, b1, bd);
    k_weff    <<<352,  256>>>(W1, Wd);
    k_pack_wc <<<1760, 256>>>(W2, Wv, b2, bv);
    k_pack_dt <<<6400, 256>>>(desc);
    k_init    <<<1536, 256>>>();

    for (int t = 0; t < T_; t++) {
        int par = t & 1;
        k_gates_lstm<<<dim3(8, 16),   256>>>(par);
        k_z         <<<dim3(8, 22),   256>>>(par, t);
        k_nxt       <<<dim3(8, 5, 4), 256>>>();
        k_reduce    <<<266, 256>>>(out, t);
    }
}